// round 5
// baseline (speedup 1.0000x reference)
#include <cuda_runtime.h>
#include <cuda_fp16.h>
#include <cstdint>

#define H     128
#define NENT  40000
#define NREL  256
#define NJ    129     // 129 att-intervals (128 breakpoints)
#define TE    8       // entities per tile in kproj2
#define TMAX  10241
#define SPB   4       // segments per kedge block

typedef unsigned long long ull;

// ---------------- scratch (device globals; no allocation) ----------------
__device__ __half2 g_Ps[NENT * H];  // {P3s, P4s} per (entity, h)  ~20.5MB
__device__ __half2 g_Pr[NREL * H];  // {P3r, P4r + W4_b}           128KB
__device__ __half2 g_AC[NJ * H];    // {A_j, C_j} piecewise table   66KB
__device__ float   g_thr[H];        // sorted breakpoints
__device__ float2  g_wqs[H * H];    // [k][h] = {W3s^T, W4s^T}
__device__ float2  g_wqr[H * H];    // [k][h] = {W3r^T, W4r^T}
__device__ int     g_off[TMAX];     // segment start offsets

__device__ __forceinline__ void fma2(ull& acc, ull a, ull b) {
    asm("fma.rn.f32x2 %0, %1, %2, %0;" : "+l"(acc) : "l"(a), "l"(b));
}

// ---------------- K0: fused setup (NJ=129 blocks x 128 threads) ----------------
// Every block recomputes breakpoints+ranks in smem (cheap, parallel).
// Block j builds AC row j; blocks j<128 also pack weight row j; block 0 writes thr.
__global__ void kSetup(const float* __restrict__ w1,
                       const float* __restrict__ b1,
                       const float* __restrict__ W3,
                       const float* __restrict__ W3b,
                       const float* __restrict__ W4) {
    __shared__ float w1s[H], b1s[H], tsh[H];
    __shared__ int rks[H];
    int h = threadIdx.x, j = blockIdx.x;
    float w = w1[h], b = b1[h];
    w1s[h] = w; b1s[h] = b;
    float t = (w != 0.0f) ? (-b / w) : __int_as_float(0x7f800000);
    tsh[h] = t;
    __syncthreads();
    int r = 0;
    #pragma unroll 8
    for (int k = 0; k < H; ++k) {
        float tk = tsh[k];
        r += (tk < t) || (tk == t && k < h);
    }
    rks[h] = r;
    if (j == 0) g_thr[r] = t;
    __syncthreads();

    // AC row j: active set = units whose relu is on in interval j
    float a = 0.0f, c = W3b[h];
    const float* row = W3 + h * 384;   // W3a = cols [0,128)
    for (int k = 0; k < H; ++k) {
        float wk = w1s[k], bk = b1s[k];
        bool act = (wk > 0.0f) ? (rks[k] < j)
                 : (wk < 0.0f) ? (rks[k] >= j)
                               : (bk > 0.0f);
        if (act) {
            float m = row[k];
            a = fmaf(m, wk, a);
            c = fmaf(m, bk, c);
        }
    }
    g_AC[j * H + h] = __floats2half2_rn(a, c);

    // pack weight row j (transpose)
    if (j < H) {
        g_wqs[j * H + h] = make_float2(W3[h * 384 + 128 + j], W4[h * 256 + j]);
        g_wqr[j * H + h] = make_float2(W3[h * 384 + 256 + j], W4[h * 256 + 128 + j]);
    }
}

// ---------------- K0d: segment offsets by boundary scatter ----------------
__global__ void kbounds2(const int* __restrict__ seg, int E, int T) {
    int i = blockIdx.x * blockDim.x + threadIdx.x;
    if (i >= E) return;
    int s = __ldg(&seg[i]);
    int sp = (i == 0) ? -1 : __ldg(&seg[i - 1]);
    for (int t = sp + 1; t <= s; ++t) g_off[t] = i;
    if (i == E - 1)
        for (int t = s + 1; t <= T; ++t) g_off[t] = E;
}

// ---------------- K1: projection, k-split, FFMA2, weights in registers --------
__global__ void __launch_bounds__(512, 1)
kproj2(const float* __restrict__ embeds,
       const ull* __restrict__ wq,     // float2 pairs as b64
       __half2* __restrict__ out,
       const float* __restrict__ b4,   // may be null
       int n) {
    __shared__ float2 emb2_sm[TE * H];       // 8 KB: duplicated {v,v}
    __shared__ float2 red[3 * TE * H];       // 24 KB: partials from ks=1,2,3
    int tid = threadIdx.x;
    int h = tid & 127;
    int ks = tid >> 7;

    ull w[32];
    #pragma unroll
    for (int j = 0; j < 32; ++j)
        w[j] = wq[(ks * 32 + j) * H + h];
    float bb = (b4 != nullptr && ks == 0) ? b4[h] : 0.0f;

    for (int tile = blockIdx.x; tile * TE < n; tile += gridDim.x) {
        int e0 = tile * TE;
        __syncthreads();
        {
            float a = embeds[(size_t)e0 * H + tid];
            float b = embeds[(size_t)e0 * H + tid + 512];
            emb2_sm[tid]       = make_float2(a, a);
            emb2_sm[tid + 512] = make_float2(b, b);
        }
        __syncthreads();

        ull acc[TE];
        #pragma unroll
        for (int e = 0; e < TE; ++e) acc[e] = 0ULL;

        #pragma unroll
        for (int j2 = 0; j2 < 16; ++j2) {
            #pragma unroll
            for (int e = 0; e < TE; ++e) {
                ulonglong2 vv = *(const ulonglong2*)&emb2_sm[e * H + ks * 32 + j2 * 2];
                fma2(acc[e], vv.x, w[j2 * 2 + 0]);
                fma2(acc[e], vv.y, w[j2 * 2 + 1]);
            }
        }

        if (ks >= 1) {
            float2* dst = red + (ks - 1) * TE * H;
            #pragma unroll
            for (int e = 0; e < TE; ++e) {
                float2 a2;
                asm("mov.b64 {%0, %1}, %2;" : "=f"(a2.x), "=f"(a2.y) : "l"(acc[e]));
                dst[e * H + h] = a2;
            }
        }
        __syncthreads();
        if (ks == 0) {
            #pragma unroll
            for (int e = 0; e < TE; ++e) {
                float2 a2;
                asm("mov.b64 {%0, %1}, %2;" : "=f"(a2.x), "=f"(a2.y) : "l"(acc[e]));
                float2 p0 = red[0 * TE * H + e * H + h];
                float2 p1 = red[1 * TE * H + e * H + h];
                float2 p2 = red[2 * TE * H + e * H + h];
                float s3 = a2.x + p0.x + p1.x + p2.x;
                float s4 = a2.y + p0.y + p1.y + p2.y + bb;
                out[(size_t)(e0 + e) * H + h] = __floats2half2_rn(s3, s4);
            }
        }
    }
}

// ---------------- K2: 4 segments/block, flat chunk staging ----------------
__global__ void __launch_bounds__(128)
kedge(const int* __restrict__ nent,
      const int* __restrict__ nrel,
      const float* __restrict__ natt,
      const float* __restrict__ self_att,
      const int* __restrict__ s_ids,
      const int* __restrict__ r_ids,
      const float* __restrict__ ent_embeds,
      const float* __restrict__ rel_embeds,
      const float* __restrict__ w1,
      const float* __restrict__ b1,
      float* __restrict__ out,
      int L, int T) {
    __shared__ float thr_sm[H];
    __shared__ int   off_s[SPB + 1];
    __shared__ int   ent_sm[128];
    __shared__ int   rel_sm[128];
    __shared__ float att_sm[128];
    __shared__ int   pos_sm[128];
    int tid = threadIdx.x;
    int t0 = blockIdx.x * SPB;
    thr_sm[tid] = g_thr[tid];
    if (tid <= SPB) off_s[tid] = g_off[t0 + tid];
    __syncthreads();
    int base = off_s[0], end = off_s[SPB];

    float acc_e[SPB], acc_s[SPB];
    #pragma unroll
    for (int s = 0; s < SPB; ++s) { acc_e[s] = 0.0f; acc_s[s] = 0.0f; }

    for (int cs = base; cs < end; cs += 128) {
        int m = min(128, end - cs);
        if (tid < m) {
            int   ent = __ldg(&nent[cs + tid]);
            int   rel = __ldg(&nrel[cs + tid]);
            float att = __ldg(&natt[cs + tid]);
            int pos = 0;
            #pragma unroll
            for (int w = 64; w >= 1; w >>= 1)
                if (thr_sm[pos + w - 1] < att) pos += w;
            ent_sm[tid] = ent; rel_sm[tid] = rel; att_sm[tid] = att; pos_sm[tid] = pos;
        }
        __syncthreads();
        #pragma unroll
        for (int s = 0; s < SPB; ++s) {
            int lo = max(off_s[s], cs) - cs;
            int hi = min(off_s[s + 1], cs + m) - cs;
            #pragma unroll 4
            for (int i = lo; i < hi; ++i) {
                int   ent = ent_sm[i];
                int   rel = rel_sm[i];
                float att = att_sm[i];
                int   pos = pos_sm[i];
                // Ps: streamed, bypass L1 (keep Pr/AC L1-resident)
                unsigned psu = __ldcg((const unsigned*)&g_Ps[(size_t)ent * H + tid]);
                float2 ps = __half22float2(*(const __half2*)&psu);
                float2 pr = __half22float2(g_Pr[(size_t)rel * H + tid]);
                float2 ac = __half22float2(g_AC[(size_t)pos * H + tid]);
                acc_e[s] += fmaxf(fmaf(att, ac.x, ac.y) + ps.x + pr.x, 0.0f);
                acc_s[s] += fmaxf(ps.y + pr.y, 0.0f);
            }
        }
        __syncthreads();
    }

    // epilogue: one output pair per segment
    float wv = w1[tid], bv = b1[tid];
    #pragma unroll
    for (int s = 0; s < SPB; ++s) {
        int t = t0 + s;
        float denom = fmaxf((float)(off_s[s + 1] - off_s[s]), 1.0f);
        float me = acc_e[s] / denom;
        float ms = acc_s[s] / denom;
        int b = t / L;
        float es = ent_embeds[(size_t)__ldg(&s_ids[b]) * H + tid];
        float er = rel_embeds[(size_t)__ldg(&r_ids[b]) * H + tid];
        float sa = __ldg(&self_att[t]);
        float sae = fmaxf(fmaf(sa, wv, bv), 0.0f);
        float* out1 = out + (size_t)t * 3 * H;
        float* out2 = out + (size_t)T * 3 * H + (size_t)t * 3 * H;
        out1[tid]         = es;
        out1[H + tid]     = er;
        out1[2 * H + tid] = ms;
        out2[tid]         = sae;
        out2[H + tid]     = es;
        out2[2 * H + tid] = me;
    }
}

// ---------------- launch ----------------
extern "C" void kernel_launch(void* const* d_in, const int* in_sizes, int n_in,
                              void* d_out, int out_size) {
    const int*   nbr_ent  = (const int*)  d_in[0];
    const int*   nbr_rel  = (const int*)  d_in[1];
    const float* nbr_att  = (const float*)d_in[2];
    const int*   seg_ids  = (const int*)  d_in[3];
    const float* self_att = (const float*)d_in[4];
    const int*   s_ids    = (const int*)  d_in[5];
    const int*   r_ids    = (const int*)  d_in[6];
    const float* ent_emb  = (const float*)d_in[7];
    const float* rel_emb  = (const float*)d_in[8];
    const float* W1w      = (const float*)d_in[9];
    const float* W1b      = (const float*)d_in[10];
    const float* W3w      = (const float*)d_in[11];
    const float* W3b      = (const float*)d_in[12];
    const float* W4w      = (const float*)d_in[13];
    const float* W4b      = (const float*)d_in[14];

    int E = in_sizes[0];
    int B = in_sizes[5];
    int L = in_sizes[4] / B;
    int T = B * L;
    int nent = in_sizes[7] / H;   // 40000
    int nrel = in_sizes[8] / H;   // 256

    void *pPs, *pPr, *pWqs, *pWqr;
    cudaGetSymbolAddress(&pPs, g_Ps);
    cudaGetSymbolAddress(&pPr, g_Pr);
    cudaGetSymbolAddress(&pWqs, g_wqs);
    cudaGetSymbolAddress(&pWqr, g_wqr);

    kSetup<<<NJ, H>>>(W1w, W1b, W3w, W3b, W4w);
    kbounds2<<<(E + 255) / 256, 256>>>(seg_ids, E, T);

    kproj2<<<148, 512>>>(ent_emb, (const ull*)pWqs, (__half2*)pPs, nullptr, nent);
    kproj2<<<32, 512>>>(rel_emb, (const ull*)pWqr, (__half2*)pPr, W4b, nrel);

    kedge<<<T / SPB, H>>>(nbr_ent, nbr_rel, nbr_att, self_att,
                          s_ids, r_ids, ent_emb, rel_emb, W1w, W1b,
                          (float*)d_out, L, T);
}

// round 7
// speedup vs baseline: 1.0242x; 1.0242x over previous
#include <cuda_runtime.h>
#include <cuda_fp16.h>
#include <cstdint>

#define H     128
#define NENT  40000
#define NREL  256
#define NJ    129     // 129 att-intervals (128 breakpoints)
#define TE    8       // entities per tile in kproj
#define TMAX  10241
#define SPB   4       // segments per kedge block

typedef unsigned long long ull;

// ---------------- scratch (device globals; no allocation) ----------------
__device__ __half2 g_Ps[NENT * H];  // {P3s, P4s} per (entity, h)  ~20.5MB
__device__ __half2 g_Pr[NREL * H];  // {P3r, P4r + W4_b}           128KB
__device__ __half2 g_AC[NJ * H];    // {A_j, C_j} piecewise table   66KB
__device__ float   g_thr[H];        // sorted breakpoints
__device__ float2  g_wqs[H * H];    // [k][h] = {W3s^T, W4s^T}
__device__ float2  g_wqr[H * H];    // [k][h] = {W3r^T, W4r^T}
__device__ int     g_off[TMAX];     // segment start offsets

__device__ __forceinline__ void fma2(ull& acc, ull a, ull b) {
    asm("fma.rn.f32x2 %0, %1, %2, %0;" : "+l"(acc) : "l"(a), "l"(b));
}

// ---------------- K0: fused setup (NJ=129 blocks x 128 threads) ----------------
__global__ void kSetup(const float* __restrict__ w1,
                       const float* __restrict__ b1,
                       const float* __restrict__ W3,
                       const float* __restrict__ W3b,
                       const float* __restrict__ W4) {
    __shared__ float w1s[H], b1s[H], tsh[H];
    __shared__ int rks[H];
    int h = threadIdx.x, j = blockIdx.x;
    float w = w1[h], b = b1[h];
    w1s[h] = w; b1s[h] = b;
    float t = (w != 0.0f) ? (-b / w) : __int_as_float(0x7f800000);
    tsh[h] = t;
    __syncthreads();
    int r = 0;
    #pragma unroll 8
    for (int k = 0; k < H; ++k) {
        float tk = tsh[k];
        r += (tk < t) || (tk == t && k < h);
    }
    rks[h] = r;
    if (j == 0) g_thr[r] = t;
    __syncthreads();

    float a = 0.0f, c = W3b[h];
    const float* row = W3 + h * 384;   // W3a = cols [0,128)
    for (int k = 0; k < H; ++k) {
        float wk = w1s[k], bk = b1s[k];
        bool act = (wk > 0.0f) ? (rks[k] < j)
                 : (wk < 0.0f) ? (rks[k] >= j)
                               : (bk > 0.0f);
        if (act) {
            float m = row[k];
            a = fmaf(m, wk, a);
            c = fmaf(m, bk, c);
        }
    }
    g_AC[j * H + h] = __floats2half2_rn(a, c);

    if (j < H) {
        g_wqs[j * H + h] = make_float2(W3[h * 384 + 128 + j], W4[h * 256 + j]);
        g_wqr[j * H + h] = make_float2(W3[h * 384 + 256 + j], W4[h * 256 + 128 + j]);
    }
}

// ---------------- K0d: segment offsets by boundary scatter ----------------
__global__ void kbounds2(const int* __restrict__ seg, int E, int T) {
    int i = blockIdx.x * blockDim.x + threadIdx.x;
    if (i >= E) return;
    int s = __ldg(&seg[i]);
    int sp = (i == 0) ? -1 : __ldg(&seg[i - 1]);
    for (int t = sp + 1; t <= s; ++t) g_off[t] = i;
    if (i == E - 1)
        for (int t = s + 1; t <= T; ++t) g_off[t] = E;
}

// ---------------- K1: merged projection (entities ++ relations) ----------------
// 512 threads: h = tid&127, ks = tid>>7. Persistent over all tiles; blocks
// crossing into the relation tile range reload their weight registers once.
__global__ void __launch_bounds__(512, 1)
kproj3(const float* __restrict__ ent_emb,
       const float* __restrict__ rel_emb,
       const ull* __restrict__ wqs,
       const ull* __restrict__ wqr,
       __half2* __restrict__ outs,
       __half2* __restrict__ outr,
       const float* __restrict__ b4,
       int n_ent, int n_rel) {
    __shared__ float2 emb2_sm[TE * H];       // 8 KB: duplicated {v,v}
    __shared__ float2 red[3 * TE * H];       // 24 KB: partials from ks=1,2,3
    int tid = threadIdx.x;
    int h = tid & 127;
    int ks = tid >> 7;
    int nt_ent = n_ent / TE;
    int nt_tot = nt_ent + n_rel / TE;

    ull w[32];
    #pragma unroll
    for (int j = 0; j < 32; ++j)
        w[j] = wqs[(ks * 32 + j) * H + h];
    float bb = 0.0f;
    bool mode_rel = false;

    for (int tile = blockIdx.x; tile < nt_tot; tile += gridDim.x) {
        bool isrel = (tile >= nt_ent);
        if (isrel && !mode_rel) {
            #pragma unroll
            for (int j = 0; j < 32; ++j)
                w[j] = wqr[(ks * 32 + j) * H + h];
            if (ks == 0) bb = b4[h];
            mode_rel = true;
        }
        const float* embeds = isrel ? rel_emb : ent_emb;
        __half2* out = isrel ? outr : outs;
        int e0 = (isrel ? tile - nt_ent : tile) * TE;

        __syncthreads();
        {
            float a = embeds[(size_t)e0 * H + tid];
            float b = embeds[(size_t)e0 * H + tid + 512];
            emb2_sm[tid]       = make_float2(a, a);
            emb2_sm[tid + 512] = make_float2(b, b);
        }
        __syncthreads();

        ull acc[TE];
        #pragma unroll
        for (int e = 0; e < TE; ++e) acc[e] = 0ULL;

        #pragma unroll
        for (int j2 = 0; j2 < 16; ++j2) {
            #pragma unroll
            for (int e = 0; e < TE; ++e) {
                ulonglong2 vv = *(const ulonglong2*)&emb2_sm[e * H + ks * 32 + j2 * 2];
                fma2(acc[e], vv.x, w[j2 * 2 + 0]);
                fma2(acc[e], vv.y, w[j2 * 2 + 1]);
            }
        }

        if (ks >= 1) {
            float2* dst = red + (ks - 1) * TE * H;
            #pragma unroll
            for (int e = 0; e < TE; ++e) {
                float2 a2;
                asm("mov.b64 {%0, %1}, %2;" : "=f"(a2.x), "=f"(a2.y) : "l"(acc[e]));
                dst[e * H + h] = a2;
            }
        }
        __syncthreads();
        if (ks == 0) {
            #pragma unroll
            for (int e = 0; e < TE; ++e) {
                float2 a2;
                asm("mov.b64 {%0, %1}, %2;" : "=f"(a2.x), "=f"(a2.y) : "l"(acc[e]));
                float2 p0 = red[0 * TE * H + e * H + h];
                float2 p1 = red[1 * TE * H + e * H + h];
                float2 p2 = red[2 * TE * H + e * H + h];
                float s3 = a2.x + p0.x + p1.x + p2.x;
                float s4 = a2.y + p0.y + p1.y + p2.y + bb;
                out[(size_t)(e0 + e) * H + h] = __floats2half2_rn(s3, s4);
            }
        }
    }
}

// ---------------- K2: 4 segments/block, packed staging, L1-cached gathers ------
__global__ void __launch_bounds__(128)
kedge(const int* __restrict__ nent,
      const int* __restrict__ nrel,
      const float* __restrict__ natt,
      const float* __restrict__ self_att,
      const int* __restrict__ s_ids,
      const int* __restrict__ r_ids,
      const float* __restrict__ ent_embeds,
      const float* __restrict__ rel_embeds,
      const float* __restrict__ w1,
      const float* __restrict__ b1,
      float* __restrict__ out,
      int L, int T) {
    __shared__ float  thr_sm[H];
    __shared__ int    off_s[SPB + 1];
    __shared__ int2   er_sm[128];    // (ent, rel)
    __shared__ float2 ap_sm[128];    // (att, pos-as-bits)
    int tid = threadIdx.x;
    int t0 = blockIdx.x * SPB;
    thr_sm[tid] = g_thr[tid];
    if (tid <= SPB) off_s[tid] = g_off[t0 + tid];
    __syncthreads();
    int base = off_s[0], end = off_s[SPB];

    float acc_e[SPB], acc_s[SPB];
    #pragma unroll
    for (int s = 0; s < SPB; ++s) { acc_e[s] = 0.0f; acc_s[s] = 0.0f; }

    for (int cs = base; cs < end; cs += 128) {
        int m = min(128, end - cs);
        if (tid < m) {
            int   ent = __ldg(&nent[cs + tid]);
            int   rel = __ldg(&nrel[cs + tid]);
            float att = __ldg(&natt[cs + tid]);
            int pos = 0;
            #pragma unroll
            for (int w = 64; w >= 1; w >>= 1)
                if (thr_sm[pos + w - 1] < att) pos += w;
            er_sm[tid] = make_int2(ent, rel);
            ap_sm[tid] = make_float2(att, __int_as_float(pos));
        }
        __syncthreads();
        #pragma unroll
        for (int s = 0; s < SPB; ++s) {
            int lo = max(off_s[s], cs) - cs;
            int hi = min(off_s[s + 1], cs + m) - cs;
            #pragma unroll 4
            for (int i = lo; i < hi; ++i) {
                int2   er = er_sm[i];
                float2 ap = ap_sm[i];
                int pos = __float_as_int(ap.y);
                float2 ps = __half22float2(__ldg(&g_Ps[(size_t)er.x * H + tid]));
                float2 pr = __half22float2(__ldg(&g_Pr[(size_t)er.y * H + tid]));
                float2 ac = __half22float2(__ldg(&g_AC[(size_t)pos * H + tid]));
                acc_e[s] += fmaxf(fmaf(ap.x, ac.x, ac.y) + ps.x + pr.x, 0.0f);
                acc_s[s] += fmaxf(ps.y + pr.y, 0.0f);
            }
        }
        __syncthreads();
    }

    float wv = w1[tid], bv = b1[tid];
    #pragma unroll
    for (int s = 0; s < SPB; ++s) {
        int t = t0 + s;
        float denom = fmaxf((float)(off_s[s + 1] - off_s[s]), 1.0f);
        float me = acc_e[s] / denom;
        float ms = acc_s[s] / denom;
        int b = t / L;
        float es = ent_embeds[(size_t)__ldg(&s_ids[b]) * H + tid];
        float er = rel_embeds[(size_t)__ldg(&r_ids[b]) * H + tid];
        float sa = __ldg(&self_att[t]);
        float sae = fmaxf(fmaf(sa, wv, bv), 0.0f);
        float* out1 = out + (size_t)t * 3 * H;
        float* out2 = out + (size_t)T * 3 * H + (size_t)t * 3 * H;
        out1[tid]         = es;
        out1[H + tid]     = er;
        out1[2 * H + tid] = ms;
        out2[tid]         = sae;
        out2[H + tid]     = es;
        out2[2 * H + tid] = me;
    }
}

// ---------------- launch ----------------
extern "C" void kernel_launch(void* const* d_in, const int* in_sizes, int n_in,
                              void* d_out, int out_size) {
    const int*   nbr_ent  = (const int*)  d_in[0];
    const int*   nbr_rel  = (const int*)  d_in[1];
    const float* nbr_att  = (const float*)d_in[2];
    const int*   seg_ids  = (const int*)  d_in[3];
    const float* self_att = (const float*)d_in[4];
    const int*   s_ids    = (const int*)  d_in[5];
    const int*   r_ids    = (const int*)  d_in[6];
    const float* ent_emb  = (const float*)d_in[7];
    const float* rel_emb  = (const float*)d_in[8];
    const float* W1w      = (const float*)d_in[9];
    const float* W1b      = (const float*)d_in[10];
    const float* W3w      = (const float*)d_in[11];
    const float* W3b      = (const float*)d_in[12];
    const float* W4w      = (const float*)d_in[13];
    const float* W4b      = (const float*)d_in[14];

    int E = in_sizes[0];
    int B = in_sizes[5];
    int L = in_sizes[4] / B;
    int T = B * L;
    int nent = in_sizes[7] / H;   // 40000
    int nrel = in_sizes[8] / H;   // 256

    void *pPs, *pPr, *pWqs, *pWqr;
    cudaGetSymbolAddress(&pPs, g_Ps);
    cudaGetSymbolAddress(&pPr, g_Pr);
    cudaGetSymbolAddress(&pWqs, g_wqs);
    cudaGetSymbolAddress(&pWqr, g_wqr);

    kSetup<<<NJ, H>>>(W1w, W1b, W3w, W3b, W4w);
    kbounds2<<<(E + 255) / 256, 256>>>(seg_ids, E, T);

    kproj3<<<148, 512>>>(ent_emb, rel_emb, (const ull*)pWqs, (const ull*)pWqr,
                         (__half2*)pPs, (__half2*)pPr, W4b, nent, nrel);

    kedge<<<T / SPB, H>>>(nbr_ent, nbr_rel, nbr_att, self_att,
                          s_ids, r_ids, ent_emb, rel_emb, W1w, W1b,
                          (float*)d_out, L, T);
}

// round 11
// speedup vs baseline: 1.4262x; 1.3925x over previous
#include <cuda_runtime.h>
#include <cuda_fp16.h>
#include <cstdint>

#define H     128
#define NENT  40000
#define NREL  256
#define NJ    129     // 129 att-intervals (128 breakpoints)
#define TMAX  10241
#define SPB   4       // segments per kedge block
#define MTILE 128

// ---------------- scratch (device globals; no allocation) ----------------
__device__ __half2 g_Ps[(NENT + MTILE) * H]; // {P3s,P4s}; padded for last tile
__device__ __half2 g_Pr[NREL * H];           // {P3r, P4r + W4_b}
__device__ __half2 g_AC[NJ * H];             // {A_j, C_j} piecewise table
__device__ float   g_thr[H];                 // sorted breakpoints
__device__ int     g_off[TMAX];              // segment start offsets
__device__ float   g_Bw[2][128 * 256];       // tf32 weights [k][n], n interleaved {P3_h,P4_h}

__device__ __forceinline__ uint32_t f2tf(float x) {
    uint32_t r;
    asm("cvt.rna.tf32.f32 %0, %1;" : "=r"(r) : "f"(x));
    return r;
}

// ---------------- K0: fused setup (NJ=129 blocks x 128 threads) ----------------
__global__ void kSetup(const float* __restrict__ w1,
                       const float* __restrict__ b1,
                       const float* __restrict__ W3,
                       const float* __restrict__ W3b,
                       const float* __restrict__ W4) {
    __shared__ float w1s[H], b1s[H], tsh[H];
    __shared__ int rks[H];
    int h = threadIdx.x, j = blockIdx.x;
    float w = w1[h], b = b1[h];
    w1s[h] = w; b1s[h] = b;
    float t = (w != 0.0f) ? (-b / w) : __int_as_float(0x7f800000);
    tsh[h] = t;
    __syncthreads();
    int r = 0;
    #pragma unroll 8
    for (int k = 0; k < H; ++k) {
        float tk = tsh[k];
        r += (tk < t) || (tk == t && k < h);
    }
    rks[h] = r;
    if (j == 0) g_thr[r] = t;
    __syncthreads();

    float a = 0.0f, c = W3b[h];
    const float* row = W3 + h * 384;   // W3a = cols [0,128)
    for (int k = 0; k < H; ++k) {
        float wk = w1s[k], bk = b1s[k];
        bool act = (wk > 0.0f) ? (rks[k] < j)
                 : (wk < 0.0f) ? (rks[k] >= j)
                               : (bk > 0.0f);
        if (act) {
            float m = row[k];
            a = fmaf(m, wk, a);
            c = fmaf(m, bk, c);
        }
    }
    g_AC[j * H + h] = __floats2half2_rn(a, c);

    // B pack: row k = j, interleaved cols {2h: P3-weight, 2h+1: P4-weight}, tf32.
    if (j < H) {
        g_Bw[0][j * 256 + 2 * h]     = __uint_as_float(f2tf(W3[h * 384 + 128 + j]));
        g_Bw[0][j * 256 + 2 * h + 1] = __uint_as_float(f2tf(W4[h * 256 + j]));
        g_Bw[1][j * 256 + 2 * h]     = __uint_as_float(f2tf(W3[h * 384 + 256 + j]));
        g_Bw[1][j * 256 + 2 * h + 1] = __uint_as_float(f2tf(W4[h * 256 + 128 + j]));
    }
}

// ---------------- K0d: segment offsets by boundary scatter ----------------
__global__ void kbounds2(const int* __restrict__ seg, int E, int T) {
    int i = blockIdx.x * blockDim.x + threadIdx.x;
    if (i >= E) return;
    int s = __ldg(&seg[i]);
    int sp = (i == 0) ? -1 : __ldg(&seg[i - 1]);
    for (int t = sp + 1; t <= s; ++t) g_off[t] = i;
    if (i == E - 1)
        for (int t = s + 1; t <= T; ++t) g_off[t] = E;
}

// ---------------- K1: tf32 mma.sync projection GEMM ----------------
// Block: 256 thr (8 warps), tile M=128 x N=128 (one n-half of 256), K=128.
// Warp wid owns rows [wid*16, wid*16+16), all 128 n-cols (16 m16n8k8 tiles).
#define AS 132
__global__ void __launch_bounds__(256, 2)
kgemm(const float* __restrict__ ent_emb, const float* __restrict__ rel_emb,
      const float* __restrict__ W4b, int n_ent, int nt_ent) {
    extern __shared__ float Asm[];   // [128][AS] tf32-converted A tile
    int tid = threadIdx.x, lane = tid & 31, wid = tid >> 5;
    int g = lane >> 2, t = lane & 3;
    int bx = blockIdx.x;
    int mt = bx >> 1, nh = bx & 1;
    bool isrel = (mt >= nt_ent);
    int m0 = (isrel ? mt - nt_ent : mt) * MTILE;
    const float* emb = isrel ? rel_emb : ent_emb;
    int mlim = isrel ? NREL : n_ent;
    const float* Bw = g_Bw[isrel ? 1 : 0];

    // stage A (coalesced LDG.128, tf32 convert, STS.128)
    #pragma unroll
    for (int i = 0; i < 16; ++i) {
        int e = i * 1024 + tid * 4;
        int r = e >> 7, c = e & 127;
        float4 v = make_float4(0.f, 0.f, 0.f, 0.f);
        if (m0 + r < mlim)
            v = __ldg((const float4*)(emb + (size_t)(m0 + r) * H + c));
        float4 o;
        o.x = __uint_as_float(f2tf(v.x));
        o.y = __uint_as_float(f2tf(v.y));
        o.z = __uint_as_float(f2tf(v.z));
        o.w = __uint_as_float(f2tf(v.w));
        *(float4*)&Asm[r * AS + c] = o;
    }
    __syncthreads();

    float acc[16][4];
    #pragma unroll
    for (int nt = 0; nt < 16; ++nt)
        #pragma unroll
        for (int q = 0; q < 4; ++q) acc[nt][q] = 0.0f;

    int msub = wid * 16;
    #pragma unroll
    for (int k0 = 0; k0 < 128; k0 += 8) {
        uint32_t a0 = __float_as_uint(Asm[(msub + g) * AS + k0 + t]);
        uint32_t a1 = __float_as_uint(Asm[(msub + g + 8) * AS + k0 + t]);
        uint32_t a2 = __float_as_uint(Asm[(msub + g) * AS + k0 + t + 4]);
        uint32_t a3 = __float_as_uint(Asm[(msub + g + 8) * AS + k0 + t + 4]);
        const float* bp = Bw + (size_t)k0 * 256 + nh * 128 + g;
        uint32_t b0[16], b1[16];
        #pragma unroll
        for (int nt = 0; nt < 16; ++nt) {
            b0[nt] = __float_as_uint(__ldg(bp + t * 256 + nt * 8));
            b1[nt] = __float_as_uint(__ldg(bp + (t + 4) * 256 + nt * 8));
        }
        #pragma unroll
        for (int nt = 0; nt < 16; ++nt) {
            asm volatile(
                "mma.sync.aligned.m16n8k8.row.col.f32.tf32.tf32.f32 "
                "{%0,%1,%2,%3}, {%4,%5,%6,%7}, {%8,%9}, {%0,%1,%2,%3};"
                : "+f"(acc[nt][0]), "+f"(acc[nt][1]), "+f"(acc[nt][2]), "+f"(acc[nt][3])
                : "r"(a0), "r"(a1), "r"(a2), "r"(a3), "r"(b0[nt]), "r"(b1[nt]));
        }
    }

    // epilogue: (c0,c1) = {P3,P4} for h = nh*64 + nt*4 + t at row m; (c2,c3) at row m+8
    __half2* dst = isrel ? g_Pr : g_Ps;
    int m = m0 + msub + g;
    #pragma unroll
    for (int nt = 0; nt < 16; ++nt) {
        int h = nh * 64 + nt * 4 + t;
        float bias = isrel ? __ldg(&W4b[h]) : 0.0f;
        dst[(size_t)m * H + h]       = __floats2half2_rn(acc[nt][0], acc[nt][1] + bias);
        dst[(size_t)(m + 8) * H + h] = __floats2half2_rn(acc[nt][2], acc[nt][3] + bias);
    }
}

// ---------------- K2: 4 segments/block, byte-offset staging ----------------
__global__ void __launch_bounds__(128)
kedge(const int* __restrict__ nent,
      const int* __restrict__ nrel,
      const float* __restrict__ natt,
      const float* __restrict__ self_att,
      const int* __restrict__ s_ids,
      const int* __restrict__ r_ids,
      const float* __restrict__ ent_embeds,
      const float* __restrict__ rel_embeds,
      const float* __restrict__ w1,
      const float* __restrict__ b1,
      float* __restrict__ out,
      int L, int T) {
    __shared__ float thr_sm[H];
    __shared__ int   off_s[SPB + 1];
    __shared__ int4  q_sm[128];      // {ent*512, rel*512, pos*512, att bits}
    int tid = threadIdx.x;
    int t0 = blockIdx.x * SPB;
    thr_sm[tid] = g_thr[tid];
    if (tid <= SPB) off_s[tid] = g_off[t0 + tid];
    __syncthreads();
    int base = off_s[0], end = off_s[SPB];
    int t4 = tid * 4;   // byte offset of this thread's half2 within a table row

    float acc_e[SPB], acc_s[SPB];
    #pragma unroll
    for (int s = 0; s < SPB; ++s) { acc_e[s] = 0.0f; acc_s[s] = 0.0f; }

    for (int cs = base; cs < end; cs += 128) {
        int m = min(128, end - cs);
        if (tid < m) {
            int   ent = __ldg(&nent[cs + tid]);
            int   rel = __ldg(&nrel[cs + tid]);
            float att = __ldg(&natt[cs + tid]);
            int pos = 0;
            #pragma unroll
            for (int w = 64; w >= 1; w >>= 1)
                if (thr_sm[pos + w - 1] < att) pos += w;
            q_sm[tid] = make_int4(ent * 512, rel * 512, pos * 512, __float_as_int(att));
        }
        __syncthreads();
        #pragma unroll
        for (int s = 0; s < SPB; ++s) {
            int lo = max(off_s[s], cs) - cs;
            int hi = min(off_s[s + 1], cs + m) - cs;
            #pragma unroll 4
            for (int i = lo; i < hi; ++i) {
                int4 q = q_sm[i];
                __half2 ps = __ldg((const __half2*)((const char*)g_Ps + (unsigned)(q.x + t4)));
                __half2 pr = __ldg((const __half2*)((const char*)g_Pr + (unsigned)(q.y + t4)));
                __half2 ac = __ldg((const __half2*)((const char*)g_AC + (unsigned)(q.z + t4)));
                float2 sp = __half22float2(__hadd2(ps, pr));
                float2 af = __half22float2(ac);
                float att = __int_as_float(q.w);
                acc_e[s] += fmaxf(fmaf(att, af.x, af.y) + sp.x, 0.0f);
                acc_s[s] += fmaxf(sp.y, 0.0f);
            }
        }
        __syncthreads();
    }

    float wv = w1[tid], bv = b1[tid];
    #pragma unroll
    for (int s = 0; s < SPB; ++s) {
        int t = t0 + s;
        float denom = fmaxf((float)(off_s[s + 1] - off_s[s]), 1.0f);
        float me = acc_e[s] / denom;
        float ms = acc_s[s] / denom;
        int b = t / L;
        float es = ent_embeds[(size_t)__ldg(&s_ids[b]) * H + tid];
        float er = rel_embeds[(size_t)__ldg(&r_ids[b]) * H + tid];
        float sa = __ldg(&self_att[t]);
        float sae = fmaxf(fmaf(sa, wv, bv), 0.0f);
        float* out1 = out + (size_t)t * 3 * H;
        float* out2 = out + (size_t)T * 3 * H + (size_t)t * 3 * H;
        out1[tid]         = es;
        out1[H + tid]     = er;
        out1[2 * H + tid] = ms;
        out2[tid]         = sae;
        out2[H + tid]     = es;
        out2[2 * H + tid] = me;
    }
}

// ---------------- launch ----------------
extern "C" void kernel_launch(void* const* d_in, const int* in_sizes, int n_in,
                              void* d_out, int out_size) {
    const int*   nbr_ent  = (const int*)  d_in[0];
    const int*   nbr_rel  = (const int*)  d_in[1];
    const float* nbr_att  = (const float*)d_in[2];
    const int*   seg_ids  = (const int*)  d_in[3];
    const float* self_att = (const float*)d_in[4];
    const int*   s_ids    = (const int*)  d_in[5];
    const int*   r_ids    = (const int*)  d_in[6];
    const float* ent_emb  = (const float*)d_in[7];
    const float* rel_emb  = (const float*)d_in[8];
    const float* W1w      = (const float*)d_in[9];
    const float* W1b      = (const float*)d_in[10];
    const float* W3w      = (const float*)d_in[11];
    const float* W3b      = (const float*)d_in[12];
    const float* W4w      = (const float*)d_in[13];
    const float* W4b      = (const float*)d_in[14];

    int E = in_sizes[0];
    int B = in_sizes[5];
    int L = in_sizes[4] / B;
    int T = B * L;
    int nent = in_sizes[7] / H;   // 40000
    int nrel = in_sizes[8] / H;   // 256

    int asm_bytes = 128 * AS * 4;   // 67584
    cudaFuncSetAttribute(kgemm, cudaFuncAttributeMaxDynamicSharedMemorySize, asm_bytes);

    kSetup<<<NJ, H>>>(W1w, W1b, W3w, W3b, W4w);
    kbounds2<<<(E + 255) / 256, 256>>>(seg_ids, E, T);

    int nt_ent = (nent + MTILE - 1) / MTILE;          // 313
    int nt_tot = nt_ent + NREL / MTILE;               // 315
    kgemm<<<nt_tot * 2, 256, asm_bytes>>>(ent_emb, rel_emb, W4b, nent, nt_ent);

    kedge<<<T / SPB, H>>>(nbr_ent, nbr_rel, nbr_att, self_att,
                          s_ids, r_ids, ent_emb, rel_emb, W1w, W1b,
                          (float*)d_out, L, T);
}

// round 12
// speedup vs baseline: 2.0248x; 1.4197x over previous
#include <cuda_runtime.h>
#include <cuda_fp16.h>
#include <cstdint>

#define H     128
#define NENT  40000
#define NREL  256
#define NJ    129     // 129 att-intervals (128 breakpoints)
#define TMAX  10241
#define SPB   4       // segments per kedge block
#define MTILE 128

// ---------------- scratch (device globals; no allocation) ----------------
__device__ __half2 g_Ps[(NENT + MTILE) * H]; // {P3s,P4s}; padded for last tile
__device__ __half2 g_Pr[NREL * H];           // {P3r, P4r + W4_b}
__device__ __half2 g_AC[NJ * H];             // {A_j, C_j} piecewise table
__device__ float   g_thr[H];                 // sorted breakpoints
__device__ int     g_off[TMAX];              // segment start offsets
// B in tf32, pre-packed in per-lane mma-fragment order:
// [mat][nh][(kk*8 + j4)*32 + lane][4]  with c = (nt&1)*2 + (b0/b1)
__device__ float   g_Bp[2][2][16 * 8 * 32 * 4];

__device__ __forceinline__ uint32_t f2tf(float x) {
    uint32_t r;
    asm("cvt.rna.tf32.f32 %0, %1;" : "=r"(r) : "f"(x));
    return r;
}

// ---------------- K0: fused setup (NJ=129 blocks x 128 threads) ----------------
__device__ __forceinline__ void bput(int mat, int k, int n, float x) {
    int nh = n >> 7, nl = n & 127;
    int g = nl & 7, nt = nl >> 3;
    int kk = k >> 3, r = k & 7;
    int b = (r >= 4) ? 1 : 0, t = r & 3;
    int lane = (g << 2) | t;
    int j4 = nt >> 1, c = ((nt & 1) << 1) | b;
    g_Bp[mat][nh][(((kk * 8 + j4) * 32) + lane) * 4 + c] = __uint_as_float(f2tf(x));
}

__global__ void kSetup(const float* __restrict__ w1,
                       const float* __restrict__ b1,
                       const float* __restrict__ W3,
                       const float* __restrict__ W3b,
                       const float* __restrict__ W4) {
    __shared__ float w1s[H], b1s[H], tsh[H];
    __shared__ int rks[H];
    int h = threadIdx.x, j = blockIdx.x;
    float w = w1[h], b = b1[h];
    w1s[h] = w; b1s[h] = b;
    float t = (w != 0.0f) ? (-b / w) : __int_as_float(0x7f800000);
    tsh[h] = t;
    __syncthreads();
    int r = 0;
    #pragma unroll 8
    for (int k = 0; k < H; ++k) {
        float tk = tsh[k];
        r += (tk < t) || (tk == t && k < h);
    }
    rks[h] = r;
    if (j == 0) g_thr[r] = t;
    __syncthreads();

    float a = 0.0f, c = W3b[h];
    const float* row = W3 + h * 384;   // W3a = cols [0,128)
    for (int k = 0; k < H; ++k) {
        float wk = w1s[k], bk = b1s[k];
        bool act = (wk > 0.0f) ? (rks[k] < j)
                 : (wk < 0.0f) ? (rks[k] >= j)
                               : (bk > 0.0f);
        if (act) {
            float m = row[k];
            a = fmaf(m, wk, a);
            c = fmaf(m, bk, c);
        }
    }
    g_AC[j * H + h] = __floats2half2_rn(a, c);

    // pack B row k=j: interleaved cols {2h: P3-weight, 2h+1: P4-weight}
    if (j < H) {
        bput(0, j, 2 * h,     W3[h * 384 + 128 + j]);
        bput(0, j, 2 * h + 1, W4[h * 256 + j]);
        bput(1, j, 2 * h,     W3[h * 384 + 256 + j]);
        bput(1, j, 2 * h + 1, W4[h * 256 + 128 + j]);
    }
}

// ---------------- K0d: segment offsets by boundary scatter ----------------
__global__ void kbounds2(const int* __restrict__ seg, int E, int T) {
    int i = blockIdx.x * blockDim.x + threadIdx.x;
    if (i >= E) return;
    int s = __ldg(&seg[i]);
    int sp = (i == 0) ? -1 : __ldg(&seg[i - 1]);
    for (int t = sp + 1; t <= s; ++t) g_off[t] = i;
    if (i == E - 1)
        for (int t = s + 1; t <= T; ++t) g_off[t] = E;
}

// ---------------- K1: tf32 mma.sync projection GEMM ----------------
// Block: 256 thr (8 warps), tile M=128 x N=128 (one n-half of 256), K=128.
// B fragments read as coalesced LDG.128 from the pre-packed layout.
#define AS 132
__global__ void __launch_bounds__(256, 2)
kgemm(const float* __restrict__ ent_emb, const float* __restrict__ rel_emb,
      const float* __restrict__ W4b, int n_ent, int nt_ent) {
    extern __shared__ float Asm[];   // [128][AS] tf32-converted A tile
    int tid = threadIdx.x, lane = tid & 31, wid = tid >> 5;
    int g = lane >> 2, t = lane & 3;
    int bx = blockIdx.x;
    int mt = bx >> 1, nh = bx & 1;
    bool isrel = (mt >= nt_ent);
    int m0 = (isrel ? mt - nt_ent : mt) * MTILE;
    const float* emb = isrel ? rel_emb : ent_emb;
    int mlim = isrel ? NREL : n_ent;
    const float4* Bp4 = (const float4*)g_Bp[isrel ? 1 : 0][nh];

    // stage A (coalesced LDG.128, tf32 convert, STS.128)
    #pragma unroll
    for (int i = 0; i < 16; ++i) {
        int e = i * 1024 + tid * 4;
        int r = e >> 7, c = e & 127;
        float4 v = make_float4(0.f, 0.f, 0.f, 0.f);
        if (m0 + r < mlim)
            v = __ldg((const float4*)(emb + (size_t)(m0 + r) * H + c));
        float4 o;
        o.x = __uint_as_float(f2tf(v.x));
        o.y = __uint_as_float(f2tf(v.y));
        o.z = __uint_as_float(f2tf(v.z));
        o.w = __uint_as_float(f2tf(v.w));
        *(float4*)&Asm[r * AS + c] = o;
    }
    __syncthreads();

    float acc[16][4];
    #pragma unroll
    for (int nt = 0; nt < 16; ++nt)
        #pragma unroll
        for (int q = 0; q < 4; ++q) acc[nt][q] = 0.0f;

    int msub = wid * 16;
    #pragma unroll
    for (int kk = 0; kk < 16; ++kk) {
        int k0 = kk * 8;
        uint32_t a0 = __float_as_uint(Asm[(msub + g) * AS + k0 + t]);
        uint32_t a1 = __float_as_uint(Asm[(msub + g + 8) * AS + k0 + t]);
        uint32_t a2 = __float_as_uint(Asm[(msub + g) * AS + k0 + t + 4]);
        uint32_t a3 = __float_as_uint(Asm[(msub + g + 8) * AS + k0 + t + 4]);
        float4 bv[8];
        #pragma unroll
        for (int j4 = 0; j4 < 8; ++j4)
            bv[j4] = __ldg(&Bp4[(kk * 8 + j4) * 32 + lane]);
        #pragma unroll
        for (int nt = 0; nt < 16; ++nt) {
            uint32_t b0 = __float_as_uint((nt & 1) ? bv[nt >> 1].z : bv[nt >> 1].x);
            uint32_t b1 = __float_as_uint((nt & 1) ? bv[nt >> 1].w : bv[nt >> 1].y);
            asm volatile(
                "mma.sync.aligned.m16n8k8.row.col.f32.tf32.tf32.f32 "
                "{%0,%1,%2,%3}, {%4,%5,%6,%7}, {%8,%9}, {%0,%1,%2,%3};"
                : "+f"(acc[nt][0]), "+f"(acc[nt][1]), "+f"(acc[nt][2]), "+f"(acc[nt][3])
                : "r"(a0), "r"(a1), "r"(a2), "r"(a3), "r"(b0), "r"(b1));
        }
    }

    // epilogue: (c0,c1) = {P3,P4} for h = nh*64 + nt*4 + t at row m; (c2,c3) at row m+8
    __half2* dst = isrel ? g_Pr : g_Ps;
    int m = m0 + msub + g;
    #pragma unroll
    for (int nt = 0; nt < 16; ++nt) {
        int h = nh * 64 + nt * 4 + t;
        float bias = isrel ? __ldg(&W4b[h]) : 0.0f;
        dst[(size_t)m * H + h]       = __floats2half2_rn(acc[nt][0], acc[nt][1] + bias);
        dst[(size_t)(m + 8) * H + h] = __floats2half2_rn(acc[nt][2], acc[nt][3] + bias);
    }
}

// ---------------- K2: 4 segments/block, 2h/thread, 2 edge-teams ----------------
__global__ void __launch_bounds__(128)
kedge(const int* __restrict__ nent,
      const int* __restrict__ nrel,
      const float* __restrict__ natt,
      const float* __restrict__ self_att,
      const int* __restrict__ s_ids,
      const int* __restrict__ r_ids,
      const float* __restrict__ ent_embeds,
      const float* __restrict__ rel_embeds,
      const float* __restrict__ w1,
      const float* __restrict__ b1,
      float* __restrict__ out,
      int L, int T) {
    __shared__ float thr_sm[H];
    __shared__ int   off_s[SPB + 1];
    __shared__ int4  q_sm[128];              // {ent*512, rel*512, pos*512, att bits}
    __shared__ float red_sm[SPB][4][64];     // team-1 partials
    int tid = threadIdx.x;
    int team = tid >> 6;                     // 0: warps 0-1, 1: warps 2-3
    int ht = tid & 63;                       // h-pair index: h = {2ht, 2ht+1}
    int ht8 = ht * 8;                        // byte offset within a 512B table row
    int t0 = blockIdx.x * SPB;
    thr_sm[tid] = g_thr[tid];
    if (tid <= SPB) off_s[tid] = g_off[t0 + tid];
    __syncthreads();
    int base = off_s[0], end = off_s[SPB];

    float acc[SPB][4];                       // {e_h0, e_h1, s_h0, s_h1}
    #pragma unroll
    for (int s = 0; s < SPB; ++s)
        #pragma unroll
        for (int q = 0; q < 4; ++q) acc[s][q] = 0.0f;

    for (int cs = base; cs < end; cs += 128) {
        int m = min(128, end - cs);
        if (tid < m) {
            int   ent = __ldg(&nent[cs + tid]);
            int   rel = __ldg(&nrel[cs + tid]);
            float att = __ldg(&natt[cs + tid]);
            int pos = 0;
            #pragma unroll
            for (int w = 64; w >= 1; w >>= 1)
                if (thr_sm[pos + w - 1] < att) pos += w;
            q_sm[tid] = make_int4(ent * 512, rel * 512, pos * 512, __float_as_int(att));
        }
        __syncthreads();
        #pragma unroll
        for (int s = 0; s < SPB; ++s) {
            int lo = max(off_s[s], cs) - cs;
            int hi = min(off_s[s + 1], cs + m) - cs;
            for (int i = lo + team; i < hi; i += 2) {
                int4 q = q_sm[i];
                uint2 ps = __ldg((const uint2*)((const char*)g_Ps + (unsigned)(q.x + ht8)));
                uint2 pr = __ldg((const uint2*)((const char*)g_Pr + (unsigned)(q.y + ht8)));
                uint2 ac = __ldg((const uint2*)((const char*)g_AC + (unsigned)(q.z + ht8)));
                __half2 sp0 = __hadd2(*(__half2*)&ps.x, *(__half2*)&pr.x);
                __half2 sp1 = __hadd2(*(__half2*)&ps.y, *(__half2*)&pr.y);
                float2 s0 = __half22float2(sp0);
                float2 s1 = __half22float2(sp1);
                float2 a0 = __half22float2(*(__half2*)&ac.x);
                float2 a1 = __half22float2(*(__half2*)&ac.y);
                float att = __int_as_float(q.w);
                acc[s][0] += fmaxf(fmaf(att, a0.x, a0.y) + s0.x, 0.0f);
                acc[s][1] += fmaxf(fmaf(att, a1.x, a1.y) + s1.x, 0.0f);
                acc[s][2] += fmaxf(s0.y, 0.0f);
                acc[s][3] += fmaxf(s1.y, 0.0f);
            }
        }
        __syncthreads();
    }

    // cross-team reduction
    if (team == 1) {
        #pragma unroll
        for (int s = 0; s < SPB; ++s)
            #pragma unroll
            for (int q = 0; q < 4; ++q) red_sm[s][q][ht] = acc[s][q];
    }
    __syncthreads();

    if (team == 0) {
        float2 wv = __ldg((const float2*)&w1[2 * ht]);
        float2 bv = __ldg((const float2*)&b1[2 * ht]);
        #pragma unroll
        for (int s = 0; s < SPB; ++s) {
            #pragma unroll
            for (int q = 0; q < 4; ++q) acc[s][q] += red_sm[s][q][ht];
            int t = t0 + s;
            float denom = fmaxf((float)(off_s[s + 1] - off_s[s]), 1.0f);
            float2 me = make_float2(acc[s][0] / denom, acc[s][1] / denom);
            float2 ms = make_float2(acc[s][2] / denom, acc[s][3] / denom);
            int b = t / L;
            float2 es = __ldg((const float2*)&ent_embeds[(size_t)__ldg(&s_ids[b]) * H + 2 * ht]);
            float2 er = __ldg((const float2*)&rel_embeds[(size_t)__ldg(&r_ids[b]) * H + 2 * ht]);
            float sa = __ldg(&self_att[t]);
            float2 sae = make_float2(fmaxf(fmaf(sa, wv.x, bv.x), 0.0f),
                                     fmaxf(fmaf(sa, wv.y, bv.y), 0.0f));
            float* out1 = out + (size_t)t * 3 * H;
            float* out2 = out + (size_t)T * 3 * H + (size_t)t * 3 * H;
            *(float2*)&out1[2 * ht]         = es;
            *(float2*)&out1[H + 2 * ht]     = er;
            *(float2*)&out1[2 * H + 2 * ht] = ms;
            *(float2*)&out2[2 * ht]         = sae;
            *(float2*)&out2[H + 2 * ht]     = es;
            *(float2*)&out2[2 * H + 2 * ht] = me;
        }
    }
}

// ---------------- launch ----------------
extern "C" void kernel_launch(void* const* d_in, const int* in_sizes, int n_in,
                              void* d_out, int out_size) {
    const int*   nbr_ent  = (const int*)  d_in[0];
    const int*   nbr_rel  = (const int*)  d_in[1];
    const float* nbr_att  = (const float*)d_in[2];
    const int*   seg_ids  = (const int*)  d_in[3];
    const float* self_att = (const float*)d_in[4];
    const int*   s_ids    = (const int*)  d_in[5];
    const int*   r_ids    = (const int*)  d_in[6];
    const float* ent_emb  = (const float*)d_in[7];
    const float* rel_emb  = (const float*)d_in[8];
    const float* W1w      = (const float*)d_in[9];
    const float* W1b      = (const float*)d_in[10];
    const float* W3w      = (const float*)d_in[11];
    const float* W3b      = (const float*)d_in[12];
    const float* W4w      = (const float*)d_in[13];
    const float* W4b      = (const float*)d_in[14];

    int E = in_sizes[0];
    int B = in_sizes[5];
    int L = in_sizes[4] / B;
    int T = B * L;
    int nent = in_sizes[7] / H;   // 40000
    int nrel = in_sizes[8] / H;   // 256

    int asm_bytes = 128 * AS * 4;   // 67584
    cudaFuncSetAttribute(kgemm, cudaFuncAttributeMaxDynamicSharedMemorySize, asm_bytes);

    kSetup<<<NJ, H>>>(W1w, W1b, W3w, W3b, W4w);
    kbounds2<<<(E + 255) / 256, 256>>>(seg_ids, E, T);

    int nt_ent = (nent + MTILE - 1) / MTILE;          // 313
    int nt_tot = nt_ent + NREL / MTILE;               // 315
    kgemm<<<nt_tot * 2, 256, asm_bytes>>>(ent_emb, rel_emb, W4b, nent, nt_ent);

    kedge<<<T / SPB, H>>>(nbr_ent, nbr_rel, nbr_att, self_att,
                          s_ids, r_ids, ent_emb, rel_emb, W1w, W1b,
                          (float*)d_out, L, T);
}